// round 2
// baseline (speedup 1.0000x reference)
#include <cuda_runtime.h>
#include <cuda_bf16.h>
#include <cstdint>

#define BSZ 8192
#define DIM 512
#define NCHUNK 8          // 512 / 64
#define TEMP_INV 2.0f
#define LOSS_EPS 1e-5f

// ---------------- scratch (device globals; allocation is forbidden) ----------------
__device__ __align__(16) __nv_bfloat16 g_Qn[BSZ * DIM];
__device__ __align__(16) __nv_bfloat16 g_Kn[BSZ * DIM];
__device__ float g_diag[BSZ];
__device__ float g_Row[BSZ];
__device__ float g_Col[BSZ];

#define SWZ(x) ((x) ^ (((x) >> 3) & 0x70))

__device__ __forceinline__ uint32_t smem_u32(const void* p) {
    uint32_t a;
    asm("{ .reg .u64 t; cvta.to.shared.u64 t, %1; cvt.u32.u64 %0, t; }"
        : "=r"(a) : "l"(p));
    return a;
}

__device__ __forceinline__ void cp_async16(uint32_t saddr, const void* gptr) {
    asm volatile("cp.async.cg.shared.global [%0], [%1], 16;"
                 :: "r"(saddr), "l"(__cvta_generic_to_global(gptr)) : "memory");
}
__device__ __forceinline__ void cp_commit() {
    asm volatile("cp.async.commit_group;" ::: "memory");
}
__device__ __forceinline__ void cp_wait1() {
    asm volatile("cp.async.wait_group 1;" ::: "memory");
}
__device__ __forceinline__ void cp_wait0() {
    asm volatile("cp.async.wait_group 0;" ::: "memory");
}

__device__ __forceinline__ void ldm_x4(uint32_t* r, uint32_t addr) {
    asm volatile("ldmatrix.sync.aligned.m8n8.x4.shared.b16 {%0,%1,%2,%3}, [%4];"
                 : "=r"(r[0]), "=r"(r[1]), "=r"(r[2]), "=r"(r[3]) : "r"(addr));
}

__device__ __forceinline__ void mma_bf16(float* c, const uint32_t* a, const uint32_t* b) {
    asm volatile(
        "mma.sync.aligned.m16n8k16.row.col.f32.bf16.bf16.f32 "
        "{%0,%1,%2,%3}, {%4,%5,%6,%7}, {%8,%9}, {%0,%1,%2,%3};"
        : "+f"(c[0]), "+f"(c[1]), "+f"(c[2]), "+f"(c[3])
        : "r"(a[0]), "r"(a[1]), "r"(a[2]), "r"(a[3]), "r"(b[0]), "r"(b[1]));
}

// ---------------- kernel 0: normalize rows, exact fp32 diag, zero accumulators ----------------
__device__ __forceinline__ float blk_sum128(float v, volatile float* sb) {
    #pragma unroll
    for (int o = 16; o; o >>= 1) v += __shfl_xor_sync(0xffffffffu, v, o);
    __syncthreads();
    if ((threadIdx.x & 31) == 0) sb[threadIdx.x >> 5] = v;
    __syncthreads();
    return (sb[0] + sb[1]) + (sb[2] + sb[3]);
}

__global__ void __launch_bounds__(128) k_norm(const float* __restrict__ q,
                                              const float* __restrict__ k,
                                              float* __restrict__ out) {
    __shared__ float sb[4];
    const int row = blockIdx.x;
    const int t = threadIdx.x;
    const float* qr = q + (size_t)row * DIM;
    const float* kr = k + (size_t)row * DIM;

    float qv[4], kv[4];
    #pragma unroll
    for (int i = 0; i < 4; i++) { qv[i] = qr[t + 128 * i]; kv[i] = kr[t + 128 * i]; }

    float sq = 0.f, sk = 0.f;
    #pragma unroll
    for (int i = 0; i < 4; i++) { sq += qv[i] * qv[i]; sk += kv[i] * kv[i]; }
    sq = blk_sum128(sq, sb);
    sk = blk_sum128(sk, sb);

    const float iq = 1.0f / fmaxf(sqrtf(sq), 1e-12f);
    const float ik = 1.0f / fmaxf(sqrtf(sk), 1e-12f);

    float dot = 0.f;
    #pragma unroll
    for (int i = 0; i < 4; i++) {
        float a = qv[i] * iq, b = kv[i] * ik;
        dot += a * b;
        g_Qn[(size_t)row * DIM + t + 128 * i] = __float2bfloat16(a);
        g_Kn[(size_t)row * DIM + t + 128 * i] = __float2bfloat16(b);
    }
    dot = blk_sum128(dot, sb);

    if (t == 0) {
        g_diag[row] = dot;
        g_Row[row] = 0.f;
        g_Col[row] = 0.f;
        if (row == 0) out[0] = 0.f;
    }
}

// ---------------- kernel 1: bf16 mma.sync GEMM + fused exp/rowsum/colsum ----------------
// CTA tile 128x128, K chunks of 64, double-buffered cp.async.
// SMEM stage: A 128x64 bf16 (16KB, 128B rows SW128) + B same. 2 stages = 64KB.
#define ST_BYTES 16384
#define SMEM_BYTES (4 * ST_BYTES)

__global__ void __launch_bounds__(256) k_gemm() {
    extern __shared__ __align__(1024) char smem[];
    const uint32_t sbase = smem_u32(smem);
    const int tid = threadIdx.x, wid = tid >> 5, lane = tid & 31;
    const int warp_m = wid & 3;          // 4 warps over M (32 rows each)
    const int warp_n = wid >> 2;         // 2 warps over N (64 cols each)
    const int ti = blockIdx.y, tj = blockIdx.x;

    const uint4* gA = (const uint4*)(g_Qn) + (size_t)ti * 128 * 64;
    const uint4* gB = (const uint4*)(g_Kn) + (size_t)tj * 128 * 64;

    // per-thread cp.async coordinates: idx = it*256+tid -> row=idx/8, ch=idx%8
    const int ld_row = tid >> 3;          // +32 per it
    const int ld_ch = tid & 7;

    auto load_stage = [&](int s) {
        const uint32_t sA = sbase + (s & 1) * 2 * ST_BYTES;
        const uint32_t sB = sA + ST_BYTES;
        #pragma unroll
        for (int it = 0; it < 4; it++) {
            const int row = ld_row + it * 32;
            const uint32_t so = SWZ(row * 128 + ld_ch * 16);
            const int go = row * 64 + s * 8 + ld_ch;
            cp_async16(sA + so, gA + go);
            cp_async16(sB + so, gB + go);
        }
        cp_commit();
    };

    // ldmatrix per-lane geometry
    const int lg = lane >> 3;                                    // 0..3
    const int a_row = warp_m * 32 + (lane & 7) + ((lg & 1) << 3);
    const int a_kb = (lg >> 1) << 4;
    const int b_row = warp_n * 64 + (lane & 7) + ((lg >> 1) << 3);
    const int b_kb = (lg & 1) << 4;

    float acc[2][8][4];
    #pragma unroll
    for (int mi = 0; mi < 2; mi++)
        #pragma unroll
        for (int ni = 0; ni < 8; ni++)
            #pragma unroll
            for (int e = 0; e < 4; e++) acc[mi][ni][e] = 0.f;

    load_stage(0);

    #pragma unroll 1
    for (int s = 0; s < NCHUNK; s++) {
        if (s + 1 < NCHUNK) { load_stage(s + 1); cp_wait1(); }
        else cp_wait0();
        __syncthreads();

        const uint32_t sA = sbase + (s & 1) * 2 * ST_BYTES;
        const uint32_t sB = sA + ST_BYTES;

        #pragma unroll
        for (int ks = 0; ks < 4; ks++) {
            const int kb = ks * 32;
            uint32_t a[2][4];
            #pragma unroll
            for (int mi = 0; mi < 2; mi++)
                ldm_x4(a[mi], sA + SWZ((a_row + mi * 16) * 128 + kb + a_kb));
            #pragma unroll
            for (int np = 0; np < 4; np++) {
                uint32_t b[4];
                ldm_x4(b, sB + SWZ((b_row + np * 16) * 128 + kb + b_kb));
                #pragma unroll
                for (int mi = 0; mi < 2; mi++) {
                    mma_bf16(acc[mi][np * 2 + 0], a[mi], b + 0);
                    mma_bf16(acc[mi][np * 2 + 1], a[mi], b + 2);
                }
            }
        }
        __syncthreads();
    }

    // ---- epilogue: exp + row/col partial sums in registers ----
    // element map: c0:(r=g, c=2q) c1:(r=g, c=2q+1) c2:(r=g+8, c=2q) c3:(r=g+8, c=2q+1)
    // with g = lane/4, q = lane%4
    float rs0[2] = {0.f, 0.f}, rs8[2] = {0.f, 0.f};
    float cs[8][2];
    #pragma unroll
    for (int ni = 0; ni < 8; ni++) cs[ni][0] = cs[ni][1] = 0.f;

    #pragma unroll
    for (int mi = 0; mi < 2; mi++)
        #pragma unroll
        for (int ni = 0; ni < 8; ni++) {
            float e0 = __expf(acc[mi][ni][0] * TEMP_INV);
            float e1 = __expf(acc[mi][ni][1] * TEMP_INV);
            float e2 = __expf(acc[mi][ni][2] * TEMP_INV);
            float e3 = __expf(acc[mi][ni][3] * TEMP_INV);
            rs0[mi] += e0 + e1;
            rs8[mi] += e2 + e3;
            cs[ni][0] += e0 + e2;
            cs[ni][1] += e1 + e3;
        }

    // row sums: reduce over lane%4 (xor 1,2)
    #pragma unroll
    for (int mi = 0; mi < 2; mi++) {
        rs0[mi] += __shfl_xor_sync(0xffffffffu, rs0[mi], 1);
        rs0[mi] += __shfl_xor_sync(0xffffffffu, rs0[mi], 2);
        rs8[mi] += __shfl_xor_sync(0xffffffffu, rs8[mi], 1);
        rs8[mi] += __shfl_xor_sync(0xffffffffu, rs8[mi], 2);
    }
    if ((lane & 3) == 0) {
        const int rbase = ti * 128 + warp_m * 32 + (lane >> 2);
        #pragma unroll
        for (int mi = 0; mi < 2; mi++) {
            atomicAdd(&g_Row[rbase + mi * 16], rs0[mi]);
            atomicAdd(&g_Row[rbase + mi * 16 + 8], rs8[mi]);
        }
    }

    // col sums: reduce over lane/4 (xor 4,8,16)
    #pragma unroll
    for (int ni = 0; ni < 8; ni++)
        #pragma unroll
        for (int j = 0; j < 2; j++) {
            cs[ni][j] += __shfl_xor_sync(0xffffffffu, cs[ni][j], 4);
            cs[ni][j] += __shfl_xor_sync(0xffffffffu, cs[ni][j], 8);
            cs[ni][j] += __shfl_xor_sync(0xffffffffu, cs[ni][j], 16);
        }
    if (lane < 4) {
        const int cbase = tj * 128 + warp_n * 64 + lane * 2;
        #pragma unroll
        for (int ni = 0; ni < 8; ni++) {
            atomicAdd(&g_Col[cbase + ni * 8], cs[ni][0]);
            atomicAdd(&g_Col[cbase + ni * 8 + 1], cs[ni][1]);
        }
    }
}

// ---------------- kernel 2: final loss ----------------
__global__ void __launch_bounds__(128) k_loss(float* __restrict__ out) {
    __shared__ float sb[4];
    const int i = blockIdx.x * 128 + threadIdx.x;
    const float rs = g_Row[i], cs = g_Col[i], d = g_diag[i];
    const float ep = __expf(d * TEMP_INV);
    float term = -logf(ep / rs + LOSS_EPS) - logf(ep / cs + LOSS_EPS);
    term = blk_sum128(term, sb);
    if (threadIdx.x == 0) atomicAdd(out, term * (1.0f / (float)BSZ));
}

// ---------------- launch ----------------
extern "C" void kernel_launch(void* const* d_in, const int* in_sizes, int n_in,
                              void* d_out, int out_size) {
    (void)in_sizes; (void)n_in; (void)out_size;
    const float* q = (const float*)d_in[0];
    const float* k = (const float*)d_in[1];
    float* out = (float*)d_out;

    cudaFuncSetAttribute(k_gemm, cudaFuncAttributeMaxDynamicSharedMemorySize, SMEM_BYTES);

    k_norm<<<BSZ, 128>>>(q, k, out);
    k_gemm<<<dim3(BSZ / 128, BSZ / 128), 256, SMEM_BYTES>>>();
    k_loss<<<BSZ / 128, 128>>>(out);
}

// round 3
// speedup vs baseline: 1.0983x; 1.0983x over previous
#include <cuda_runtime.h>
#include <cuda.h>
#include <cuda_bf16.h>
#include <cstdint>

#define BSZ 8192
#define DIM 512
#define TM 128
#define TN 256
#define NCHUNK 8            // 512 / 64 K per stage
#define NSTAGE 4
#define STAGE_BYTES 49152   // A 16KB + B 32KB
#define SMEM_BYTES (1024 + NSTAGE * STAGE_BYTES)
#define TEMP_INV 2.0f
#define LOSS_EPS 1e-5f

// ---------------- scratch (device globals; allocation is forbidden) ----------------
__device__ __align__(1024) __nv_bfloat16 g_Qn[BSZ * DIM];
__device__ __align__(1024) __nv_bfloat16 g_Kn[BSZ * DIM];
__device__ float g_diag[BSZ];
__device__ float g_Row[BSZ];
__device__ float g_Col[BSZ];

#define SWZ(x) ((x) ^ (((x) >> 3) & 0x70))

__device__ __forceinline__ uint32_t smem_u32(const void* p) {
    uint32_t a;
    asm("{ .reg .u64 t; cvta.to.shared.u64 t, %1; cvt.u32.u64 %0, t; }"
        : "=r"(a) : "l"(p));
    return a;
}

__device__ __forceinline__ void ldm_x4(uint32_t* r, uint32_t addr) {
    asm volatile("ldmatrix.sync.aligned.m8n8.x4.shared.b16 {%0,%1,%2,%3}, [%4];"
                 : "=r"(r[0]), "=r"(r[1]), "=r"(r[2]), "=r"(r[3]) : "r"(addr));
}

__device__ __forceinline__ void mma_bf16(float* c, const uint32_t* a, const uint32_t* b) {
    asm volatile(
        "mma.sync.aligned.m16n8k16.row.col.f32.bf16.bf16.f32 "
        "{%0,%1,%2,%3}, {%4,%5,%6,%7}, {%8,%9}, {%0,%1,%2,%3};"
        : "+f"(c[0]), "+f"(c[1]), "+f"(c[2]), "+f"(c[3])
        : "r"(a[0]), "r"(a[1]), "r"(a[2]), "r"(a[3]), "r"(b[0]), "r"(b[1]));
}

__device__ __forceinline__ void mbar_init(uint32_t mbar, uint32_t cnt) {
    asm volatile("mbarrier.init.shared.b64 [%0], %1;" :: "r"(mbar), "r"(cnt) : "memory");
}
__device__ __forceinline__ void mbar_expect_tx(uint32_t mbar, uint32_t bytes) {
    asm volatile("mbarrier.arrive.expect_tx.shared.b64 _, [%0], %1;"
                 :: "r"(mbar), "r"(bytes) : "memory");
}
__device__ __forceinline__ void mbar_arrive(uint32_t mbar) {
    asm volatile("mbarrier.arrive.shared.b64 _, [%0];" :: "r"(mbar) : "memory");
}
__device__ __forceinline__ void mbar_wait(uint32_t mbar, uint32_t parity) {
    uint32_t done;
    asm volatile(
        "{\n\t.reg .pred p;\n\t"
        "mbarrier.try_wait.parity.acquire.cta.shared::cta.b64 p, [%1], %2;\n\t"
        "selp.b32 %0, 1, 0, p;\n\t}"
        : "=r"(done) : "r"(mbar), "r"(parity) : "memory");
    if (!done) {
        asm volatile(
            "{\n\t.reg .pred P1;\n\t"
            "W_LOOP_%=:\n\t"
            "mbarrier.try_wait.parity.acquire.cta.shared::cta.b64 P1, [%0], %1, 0x989680;\n\t"
            "@P1 bra.uni W_DONE_%=;\n\t"
            "bra.uni W_LOOP_%=;\n\t"
            "W_DONE_%=:\n\t}"
            :: "r"(mbar), "r"(parity) : "memory");
    }
}
__device__ __forceinline__ void tma_2d(uint32_t saddr, const CUtensorMap* tmap,
                                       int x, int y, uint32_t mbar) {
    asm volatile(
        "cp.async.bulk.tensor.2d.shared::cta.global.tile.mbarrier::complete_tx::bytes "
        "[%0], [%1, {%2, %3}], [%4];"
        :: "r"(saddr), "l"(tmap), "r"(x), "r"(y), "r"(mbar) : "memory");
}

// ---------------- kernel 0: normalize rows, exact fp32 diag, zero accumulators ----------------
__device__ __forceinline__ float blk_sum128(float v, volatile float* sb) {
    #pragma unroll
    for (int o = 16; o; o >>= 1) v += __shfl_xor_sync(0xffffffffu, v, o);
    __syncthreads();
    if ((threadIdx.x & 31) == 0) sb[threadIdx.x >> 5] = v;
    __syncthreads();
    return (sb[0] + sb[1]) + (sb[2] + sb[3]);
}

__global__ void __launch_bounds__(128) k_norm(const float* __restrict__ q,
                                              const float* __restrict__ k,
                                              float* __restrict__ out) {
    __shared__ float sb[4];
    const int row = blockIdx.x;
    const int t = threadIdx.x;
    const float* qr = q + (size_t)row * DIM;
    const float* kr = k + (size_t)row * DIM;

    float qv[4], kv[4];
    #pragma unroll
    for (int i = 0; i < 4; i++) { qv[i] = qr[t + 128 * i]; kv[i] = kr[t + 128 * i]; }

    float sq = 0.f, sk = 0.f;
    #pragma unroll
    for (int i = 0; i < 4; i++) { sq += qv[i] * qv[i]; sk += kv[i] * kv[i]; }
    sq = blk_sum128(sq, sb);
    sk = blk_sum128(sk, sb);

    const float iq = 1.0f / fmaxf(sqrtf(sq), 1e-12f);
    const float ik = 1.0f / fmaxf(sqrtf(sk), 1e-12f);

    float dot = 0.f;
    #pragma unroll
    for (int i = 0; i < 4; i++) {
        float a = qv[i] * iq, b = kv[i] * ik;
        dot += a * b;
        g_Qn[(size_t)row * DIM + t + 128 * i] = __float2bfloat16(a);
        g_Kn[(size_t)row * DIM + t + 128 * i] = __float2bfloat16(b);
    }
    dot = blk_sum128(dot, sb);

    if (t == 0) {
        g_diag[row] = dot;
        g_Row[row] = 0.f;
        g_Col[row] = 0.f;
        if (row == 0) out[0] = 0.f;
    }
}

// ---------------- kernel 1: 128x256 tile, TMA 4-stage ring, mma.sync, fused epilogue ----------------
__global__ void __launch_bounds__(256, 1) k_gemm(const __grid_constant__ CUtensorMap tmapA,
                                                const __grid_constant__ CUtensorMap tmapB) {
    extern __shared__ __align__(1024) char smem[];
    const uint32_t sbase = smem_u32(smem);
    const int tid = threadIdx.x, wid = tid >> 5, lane = tid & 31;
    const int warp_m = wid & 1;          // 2 warps over M (64 rows each)
    const int warp_n = wid >> 1;         // 4 warps over N (64 cols each)
    const int ti = blockIdx.y, tj = blockIdx.x;

    // mbarriers: full[s] at s*16, empty[s] at s*16+8
    if (tid == 0) {
        #pragma unroll
        for (int s = 0; s < NSTAGE; s++) {
            mbar_init(sbase + s * 16, 1);        // full: tx-based
            mbar_init(sbase + s * 16 + 8, 256);  // empty: all threads arrive
        }
    }
    __syncthreads();

    // prologue: fill all 4 stages
    if (tid == 0) {
        #pragma unroll
        for (int c = 0; c < NSTAGE; c++) {
            const uint32_t stA = sbase + 1024 + c * STAGE_BYTES;
            const uint32_t fullb = sbase + c * 16;
            mbar_expect_tx(fullb, STAGE_BYTES);
            tma_2d(stA, &tmapA, c * 64, ti * TM, fullb);
            tma_2d(stA + 16384, &tmapB, c * 64, tj * TN, fullb);
        }
    }

    // ldmatrix per-lane geometry (verified mapping from round 2)
    const int lg = lane >> 3;
    const int a_row = warp_m * 64 + (lane & 7) + ((lg & 1) << 3);
    const int a_kb = (lg >> 1) << 4;
    const int b_row = warp_n * 64 + (lane & 7) + ((lg >> 1) << 3);
    const int b_kb = (lg & 1) << 4;

    float acc[4][8][4];
    #pragma unroll
    for (int mi = 0; mi < 4; mi++)
        #pragma unroll
        for (int ni = 0; ni < 8; ni++)
            #pragma unroll
            for (int e = 0; e < 4; e++) acc[mi][ni][e] = 0.f;

    #pragma unroll 1
    for (int c = 0; c < NCHUNK; c++) {
        const int s = c & (NSTAGE - 1);
        const uint32_t fullb = sbase + s * 16;
        const uint32_t emptyb = fullb + 8;
        mbar_wait(fullb, (c >> 2) & 1);

        const uint32_t sA = sbase + 1024 + s * STAGE_BYTES;
        const uint32_t sB = sA + 16384;

        #pragma unroll
        for (int ks = 0; ks < 4; ks++) {
            const int kb = ks * 32;
            uint32_t a[4][4];
            #pragma unroll
            for (int mi = 0; mi < 4; mi++)
                ldm_x4(a[mi], sA + SWZ((a_row + mi * 16) * 128 + kb + a_kb));
            #pragma unroll
            for (int np = 0; np < 4; np++) {
                uint32_t b[4];
                ldm_x4(b, sB + SWZ((b_row + np * 16) * 128 + kb + b_kb));
                #pragma unroll
                for (int mi = 0; mi < 4; mi++) {
                    mma_bf16(acc[mi][np * 2 + 0], a[mi], b + 0);
                    mma_bf16(acc[mi][np * 2 + 1], a[mi], b + 2);
                }
            }
        }

        mbar_arrive(emptyb);
        if (tid == 0 && c + NSTAGE < NCHUNK) {
            mbar_wait(emptyb, 0);   // single reuse round -> parity 0
            const int cn = c + NSTAGE;
            mbar_expect_tx(fullb, STAGE_BYTES);
            tma_2d(sA, &tmapA, cn * 64, ti * TM, fullb);
            tma_2d(sB, &tmapB, cn * 64, tj * TN, fullb);
        }
    }

    // ---- epilogue: exp + row/col sums, register-level reductions ----
    float rs0[4] = {0.f, 0.f, 0.f, 0.f}, rs8[4] = {0.f, 0.f, 0.f, 0.f};
    float cs[8][2];
    #pragma unroll
    for (int ni = 0; ni < 8; ni++) cs[ni][0] = cs[ni][1] = 0.f;

    #pragma unroll
    for (int mi = 0; mi < 4; mi++)
        #pragma unroll
        for (int ni = 0; ni < 8; ni++) {
            float e0 = __expf(acc[mi][ni][0] * TEMP_INV);
            float e1 = __expf(acc[mi][ni][1] * TEMP_INV);
            float e2 = __expf(acc[mi][ni][2] * TEMP_INV);
            float e3 = __expf(acc[mi][ni][3] * TEMP_INV);
            rs0[mi] += e0 + e1;
            rs8[mi] += e2 + e3;
            cs[ni][0] += e0 + e2;
            cs[ni][1] += e1 + e3;
        }

    #pragma unroll
    for (int mi = 0; mi < 4; mi++) {
        rs0[mi] += __shfl_xor_sync(0xffffffffu, rs0[mi], 1);
        rs0[mi] += __shfl_xor_sync(0xffffffffu, rs0[mi], 2);
        rs8[mi] += __shfl_xor_sync(0xffffffffu, rs8[mi], 1);
        rs8[mi] += __shfl_xor_sync(0xffffffffu, rs8[mi], 2);
    }
    if ((lane & 3) == 0) {
        const int rbase = ti * TM + warp_m * 64 + (lane >> 2);
        #pragma unroll
        for (int mi = 0; mi < 4; mi++) {
            atomicAdd(&g_Row[rbase + mi * 16], rs0[mi]);
            atomicAdd(&g_Row[rbase + mi * 16 + 8], rs8[mi]);
        }
    }

    #pragma unroll
    for (int ni = 0; ni < 8; ni++)
        #pragma unroll
        for (int j = 0; j < 2; j++) {
            cs[ni][j] += __shfl_xor_sync(0xffffffffu, cs[ni][j], 4);
            cs[ni][j] += __shfl_xor_sync(0xffffffffu, cs[ni][j], 8);
            cs[ni][j] += __shfl_xor_sync(0xffffffffu, cs[ni][j], 16);
        }
    if (lane < 4) {
        const int cbase = tj * TN + warp_n * 64 + lane * 2;
        #pragma unroll
        for (int ni = 0; ni < 8; ni++) {
            atomicAdd(&g_Col[cbase + ni * 8], cs[ni][0]);
            atomicAdd(&g_Col[cbase + ni * 8 + 1], cs[ni][1]);
        }
    }
}

// ---------------- kernel 2: final loss ----------------
__global__ void __launch_bounds__(128) k_loss(float* __restrict__ out) {
    __shared__ float sb[4];
    const int i = blockIdx.x * 128 + threadIdx.x;
    const float rs = g_Row[i], cs = g_Col[i], d = g_diag[i];
    const float ep = __expf(d * TEMP_INV);
    float term = -logf(ep / rs + LOSS_EPS) - logf(ep / cs + LOSS_EPS);
    term = blk_sum128(term, sb);
    if (threadIdx.x == 0) atomicAdd(out, term * (1.0f / (float)BSZ));
}

// ---------------- launch ----------------
typedef CUresult (*PFN_encodeTiled)(CUtensorMap*, CUtensorMapDataType, cuuint32_t, void*,
                                    const cuuint64_t*, const cuuint64_t*, const cuuint32_t*,
                                    const cuuint32_t*, CUtensorMapInterleave, CUtensorMapSwizzle,
                                    CUtensorMapL2promotion, CUtensorMapFloatOOBfill);

extern "C" void kernel_launch(void* const* d_in, const int* in_sizes, int n_in,
                              void* d_out, int out_size) {
    (void)in_sizes; (void)n_in; (void)out_size;
    const float* q = (const float*)d_in[0];
    const float* k = (const float*)d_in[1];
    float* out = (float*)d_out;

    void* fn = nullptr;
    cudaDriverEntryPointQueryResult st;
    cudaGetDriverEntryPoint("cuTensorMapEncodeTiled", &fn, cudaEnableDefault, &st);
    PFN_encodeTiled encode = (PFN_encodeTiled)fn;

    void *pQ = nullptr, *pK = nullptr;
    cudaGetSymbolAddress(&pQ, g_Qn);
    cudaGetSymbolAddress(&pK, g_Kn);

    cuuint64_t dims[2] = {DIM, BSZ};
    cuuint64_t strides[1] = {DIM * sizeof(__nv_bfloat16)};
    cuuint32_t boxA[2] = {64, TM};
    cuuint32_t boxB[2] = {64, TN};
    cuuint32_t es[2] = {1, 1};

    CUtensorMap tA, tB;
    encode(&tA, CU_TENSOR_MAP_DATA_TYPE_BFLOAT16, 2, pQ, dims, strides, boxA, es,
           CU_TENSOR_MAP_INTERLEAVE_NONE, CU_TENSOR_MAP_SWIZZLE_128B,
           CU_TENSOR_MAP_L2_PROMOTION_L2_128B, CU_TENSOR_MAP_FLOAT_OOB_FILL_NONE);
    encode(&tB, CU_TENSOR_MAP_DATA_TYPE_BFLOAT16, 2, pK, dims, strides, boxB, es,
           CU_TENSOR_MAP_INTERLEAVE_NONE, CU_TENSOR_MAP_SWIZZLE_128B,
           CU_TENSOR_MAP_L2_PROMOTION_L2_128B, CU_TENSOR_MAP_FLOAT_OOB_FILL_NONE);

    cudaFuncSetAttribute(k_gemm, cudaFuncAttributeMaxDynamicSharedMemorySize, SMEM_BYTES);

    k_norm<<<BSZ, 128>>>(q, k, out);
    k_gemm<<<dim3(BSZ / TN, BSZ / TM), 256, SMEM_BYTES>>>(tA, tB);
    k_loss<<<BSZ / 128, 128>>>(out);
}

// round 6
// speedup vs baseline: 1.6002x; 1.4570x over previous
#include <cuda_runtime.h>
#include <cuda.h>
#include <cuda_bf16.h>
#include <cstdint>

#define BSZ 8192
#define DIM 512
#define TM 128
#define TN 256
#define NCHUNK 4            // 512 int8 / 128 bytes per stage
#define NSTAGE 4            // == NCHUNK: no buffer recycling needed
#define STA 16384           // A stage: 128 rows x 128 B
#define STB 32768           // B stage: 256 rows x 128 B
#define STAGE_BYTES (STA + STB)
#define SMEM_BYTES (1024 + NSTAGE * STAGE_BYTES)
#define TEMP_INV 2.0f
#define LOSS_EPS 1e-5f

// ---------------- scratch (device globals; allocation is forbidden) ----------------
__device__ __align__(1024) signed char g_Q8[BSZ * DIM];
__device__ __align__(1024) signed char g_K8[BSZ * DIM];
__device__ float g_Sq[BSZ];   // dequant scale per q row (max/127)
__device__ float g_Sk[BSZ];
__device__ float g_diag[BSZ];
__device__ float g_Row[BSZ];
__device__ float g_Col[BSZ];

#define SWZ(x) ((x) ^ (((x) >> 3) & 0x70))

static __device__ __forceinline__ uint32_t smem_u32(const void* p) {
    uint32_t a;
    asm("{ .reg .u64 t; cvta.to.shared.u64 t, %1; cvt.u32.u64 %0, t; }"
        : "=r"(a) : "l"(p));
    return a;
}

static __device__ __forceinline__ void ldm_x4(uint32_t* r, uint32_t addr) {
    asm volatile("ldmatrix.sync.aligned.m8n8.x4.shared.b16 {%0,%1,%2,%3}, [%4];"
                 : "=r"(r[0]), "=r"(r[1]), "=r"(r[2]), "=r"(r[3]) : "r"(addr));
}

static __device__ __forceinline__ void mma_s8(int* c, const uint32_t* a, const uint32_t* b) {
    asm volatile(
        "mma.sync.aligned.m16n8k32.row.col.s32.s8.s8.s32 "
        "{%0,%1,%2,%3}, {%4,%5,%6,%7}, {%8,%9}, {%0,%1,%2,%3};"
        : "+r"(c[0]), "+r"(c[1]), "+r"(c[2]), "+r"(c[3])
        : "r"(a[0]), "r"(a[1]), "r"(a[2]), "r"(a[3]), "r"(b[0]), "r"(b[1]));
}

static __device__ __forceinline__ void mbar_init(uint32_t mbar, uint32_t cnt) {
    asm volatile("mbarrier.init.shared.b64 [%0], %1;" :: "r"(mbar), "r"(cnt) : "memory");
}
static __device__ __forceinline__ void mbar_expect_tx(uint32_t mbar, uint32_t bytes) {
    asm volatile("mbarrier.arrive.expect_tx.shared.b64 _, [%0], %1;"
                 :: "r"(mbar), "r"(bytes) : "memory");
}
static __device__ __forceinline__ void mbar_wait(uint32_t mbar, uint32_t parity) {
    uint32_t done;
    asm volatile(
        "{\n\t.reg .pred p;\n\t"
        "mbarrier.try_wait.parity.acquire.cta.shared::cta.b64 p, [%1], %2;\n\t"
        "selp.b32 %0, 1, 0, p;\n\t}"
        : "=r"(done) : "r"(mbar), "r"(parity) : "memory");
    if (!done) {
        asm volatile(
            "{\n\t.reg .pred P1;\n\t"
            "W_LOOP_%=:\n\t"
            "mbarrier.try_wait.parity.acquire.cta.shared::cta.b64 P1, [%0], %1, 0x989680;\n\t"
            "@P1 bra.uni W_DONE_%=;\n\t"
            "bra.uni W_LOOP_%=;\n\t"
            "W_DONE_%=:\n\t}"
            :: "r"(mbar), "r"(parity) : "memory");
    }
}
static __device__ __forceinline__ void tma_2d(uint32_t saddr, const CUtensorMap* tmap,
                                              int x, int y, uint32_t mbar) {
    asm volatile(
        "cp.async.bulk.tensor.2d.shared::cta.global.tile.mbarrier::complete_tx::bytes "
        "[%0], [%1, {%2, %3}], [%4];"
        :: "r"(saddr), "l"(tmap), "r"(x), "r"(y), "r"(mbar) : "memory");
}

// ---------------- kernel 0: normalize, fp32 diag, int8 quantize + scales ----------------
static __device__ __forceinline__ float blk_red128(float v, volatile float* sb, bool ismax) {
    #pragma unroll
    for (int o = 16; o; o >>= 1) {
        float u = __shfl_xor_sync(0xffffffffu, v, o);
        v = ismax ? fmaxf(v, u) : (v + u);
    }
    __syncthreads();
    if ((threadIdx.x & 31) == 0) sb[threadIdx.x >> 5] = v;
    __syncthreads();
    return ismax ? fmaxf(fmaxf(sb[0], sb[1]), fmaxf(sb[2], sb[3]))
                 : (sb[0] + sb[1]) + (sb[2] + sb[3]);
}

__global__ void __launch_bounds__(128) k_norm(const float* __restrict__ q,
                                              const float* __restrict__ k,
                                              float* __restrict__ out) {
    __shared__ float sb[4];
    const int row = blockIdx.x;
    const int t = threadIdx.x;
    const float4 q4 = ((const float4*)(q + (size_t)row * DIM))[t];
    const float4 k4 = ((const float4*)(k + (size_t)row * DIM))[t];
    float a[4] = {q4.x, q4.y, q4.z, q4.w};
    float b[4] = {k4.x, k4.y, k4.z, k4.w};

    float sq = 0.f, sk = 0.f;
    #pragma unroll
    for (int i = 0; i < 4; i++) { sq += a[i] * a[i]; sk += b[i] * b[i]; }
    sq = blk_red128(sq, sb, false);
    sk = blk_red128(sk, sb, false);
    const float iq = 1.0f / fmaxf(sqrtf(sq), 1e-12f);
    const float ik = 1.0f / fmaxf(sqrtf(sk), 1e-12f);

    float dot = 0.f, mq = 0.f, mk = 0.f;
    #pragma unroll
    for (int i = 0; i < 4; i++) {
        a[i] *= iq; b[i] *= ik;
        dot += a[i] * b[i];
        mq = fmaxf(mq, fabsf(a[i]));
        mk = fmaxf(mk, fabsf(b[i]));
    }
    dot = blk_red128(dot, sb, false);
    mq = fmaxf(blk_red128(mq, sb, true), 1e-20f);
    mk = fmaxf(blk_red128(mk, sb, true), 1e-20f);

    const float qinvA = 127.0f / mq, qinvB = 127.0f / mk;
    char4 ca, cb;
    ca.x = (char)__float2int_rn(a[0] * qinvA);
    ca.y = (char)__float2int_rn(a[1] * qinvA);
    ca.z = (char)__float2int_rn(a[2] * qinvA);
    ca.w = (char)__float2int_rn(a[3] * qinvA);
    cb.x = (char)__float2int_rn(b[0] * qinvB);
    cb.y = (char)__float2int_rn(b[1] * qinvB);
    cb.z = (char)__float2int_rn(b[2] * qinvB);
    cb.w = (char)__float2int_rn(b[3] * qinvB);
    ((char4*)g_Q8)[(size_t)row * 128 + t] = ca;
    ((char4*)g_K8)[(size_t)row * 128 + t] = cb;

    if (t == 0) {
        g_Sq[row] = mq * (1.0f / 127.0f);
        g_Sk[row] = mk * (1.0f / 127.0f);
        g_diag[row] = dot;
        g_Row[row] = 0.f;
        g_Col[row] = 0.f;
        if (row == 0) out[0] = 0.f;
    }
}

// ---------------- kernel 1: int8 IMMA 128x256, 4-stage TMA (no recycle), fused epilogue ----
__global__ void __launch_bounds__(256, 1) k_gemm(const __grid_constant__ CUtensorMap tmapA,
                                                const __grid_constant__ CUtensorMap tmapB) {
    extern __shared__ __align__(1024) char smem[];
    const uint32_t sbase = smem_u32(smem);
    const int tid = threadIdx.x, wid = tid >> 5, lane = tid & 31;
    const int warp_m = wid & 1;          // 2 warps over M (64 rows)
    const int warp_n = wid >> 1;         // 4 warps over N (64 cols)
    const int ti = blockIdx.y, tj = blockIdx.x;

    if (tid == 0) {
        #pragma unroll
        for (int s = 0; s < NSTAGE; s++) mbar_init(sbase + s * 16, 1);
    }
    __syncthreads();

    if (tid == 0) {
        #pragma unroll
        for (int c = 0; c < NSTAGE; c++) {
            const uint32_t stA = sbase + 1024 + c * STAGE_BYTES;
            const uint32_t fullb = sbase + c * 16;
            mbar_expect_tx(fullb, STAGE_BYTES);
            tma_2d(stA, &tmapA, c * 128, ti * TM, fullb);
            tma_2d(stA + STA, &tmapB, c * 128, tj * TN, fullb);
        }
    }

    // ldmatrix geometry: byte-identical to the verified b16-k16 mapping
    const int lg = lane >> 3;
    const int a_row = warp_m * 64 + (lane & 7) + ((lg & 1) << 3);
    const int a_kb = (lg >> 1) << 4;
    const int b_row = warp_n * 64 + (lane & 7) + ((lg >> 1) << 3);
    const int b_kb = (lg & 1) << 4;

    int acc[4][8][4];
    #pragma unroll
    for (int mi = 0; mi < 4; mi++)
        #pragma unroll
        for (int ni = 0; ni < 8; ni++)
            #pragma unroll
            for (int e = 0; e < 4; e++) acc[mi][ni][e] = 0;

    #pragma unroll 1
    for (int c = 0; c < NCHUNK; c++) {
        const uint32_t fullb = sbase + c * 16;
        mbar_wait(fullb, 0);
        const uint32_t sA = sbase + 1024 + c * STAGE_BYTES;
        const uint32_t sB = sA + STA;

        #pragma unroll
        for (int ks = 0; ks < 4; ks++) {
            const int kb = ks * 32;                 // 32 bytes = k32 int8
            uint32_t a[4][4];
            #pragma unroll
            for (int mi = 0; mi < 4; mi++)
                ldm_x4(a[mi], sA + SWZ((a_row + mi * 16) * 128 + kb + a_kb));
            #pragma unroll
            for (int np = 0; np < 4; np++) {
                uint32_t b[4];
                ldm_x4(b, sB + SWZ((b_row + np * 16) * 128 + kb + b_kb));
                #pragma unroll
                for (int mi = 0; mi < 4; mi++) {
                    mma_s8(acc[mi][np * 2 + 0], a[mi], b + 0);
                    mma_s8(acc[mi][np * 2 + 1], a[mi], b + 2);
                }
            }
        }
    }

    // ---- epilogue: dequant + exp + row/col sums ----
    const int g = lane >> 2, qq = lane & 3;
    float rA[4][2], rB[8][2];
    #pragma unroll
    for (int mi = 0; mi < 4; mi++) {
        const int r0 = ti * TM + warp_m * 64 + mi * 16 + g;
        rA[mi][0] = g_Sq[r0] * TEMP_INV;
        rA[mi][1] = g_Sq[r0 + 8] * TEMP_INV;
    }
    #pragma unroll
    for (int ni = 0; ni < 8; ni++) {
        const int c0 = tj * TN + warp_n * 64 + ni * 8 + qq * 2;
        rB[ni][0] = g_Sk[c0];
        rB[ni][1] = g_Sk[c0 + 1];
    }

    float rs0[4] = {0.f, 0.f, 0.f, 0.f}, rs8[4] = {0.f, 0.f, 0.f, 0.f};
    float cs[8][2];
    #pragma unroll
    for (int ni = 0; ni < 8; ni++) cs[ni][0] = cs[ni][1] = 0.f;

    #pragma unroll
    for (int mi = 0; mi < 4; mi++)
        #pragma unroll
        for (int ni = 0; ni < 8; ni++) {
            float e0 = __expf((float)acc[mi][ni][0] * (rA[mi][0] * rB[ni][0]));
            float e1 = __expf((float)acc[mi][ni][1] * (rA[mi][0] * rB[ni][1]));
            float e2 = __expf((float)acc[mi][ni][2] * (rA[mi][1] * rB[ni][0]));
            float e3 = __expf((float)acc[mi][ni][3] * (rA[mi][1] * rB[ni][1]));
            rs0[mi] += e0 + e1;
            rs8[mi] += e2 + e3;
            cs[ni][0] += e0 + e2;
            cs[ni][1] += e1 + e3;
        }

    #pragma unroll
    for (int mi = 0; mi < 4; mi++) {
        rs0[mi] += __shfl_xor_sync(0xffffffffu, rs0[mi], 1);
        rs0[mi] += __shfl_xor_sync(0xffffffffu, rs0[mi], 2);
        rs8[mi] += __shfl_xor_sync(0xffffffffu, rs8[mi], 1);
        rs8[mi] += __shfl_xor_sync(0xffffffffu, rs8[mi], 2);
    }
    if ((lane & 3) == 0) {
        const int rbase = ti * TM + warp_m * 64 + g;
        #pragma unroll
        for (int mi = 0; mi < 4; mi++) {
            atomicAdd(&g_Row[rbase + mi * 16], rs0[mi]);
            atomicAdd(&g_Row[rbase + mi * 16 + 8], rs8[mi]);
        }
    }

    #pragma unroll
    for (int ni = 0; ni < 8; ni++)
        #pragma unroll
        for (int j = 0; j < 2; j++) {
            cs[ni][j] += __shfl_xor_sync(0xffffffffu, cs[ni][j], 4);
            cs[ni][j] += __shfl_xor_sync(0xffffffffu, cs[ni][j], 8);
            cs[ni][j] += __shfl_xor_sync(0xffffffffu, cs[ni][j], 16);
        }
    if (lane < 4) {
        const int cbase = tj * TN + warp_n * 64 + lane * 2;
        #pragma unroll
        for (int ni = 0; ni < 8; ni++) {
            atomicAdd(&g_Col[cbase + ni * 8], cs[ni][0]);
            atomicAdd(&g_Col[cbase + ni * 8 + 1], cs[ni][1]);
        }
    }
}

// ---------------- kernel 2: final loss ----------------
__global__ void __launch_bounds__(128) k_loss(float* __restrict__ out) {
    __shared__ float sb[4];
    const int i = blockIdx.x * 128 + threadIdx.x;
    const float rs = g_Row[i], cs = g_Col[i], d = g_diag[i];
    const float ep = __expf(d * TEMP_INV);
    float term = -logf(ep / rs + LOSS_EPS) - logf(ep / cs + LOSS_EPS);
    term = blk_red128(term, sb, false);
    if (threadIdx.x == 0) atomicAdd(out, term * (1.0f / (float)BSZ));
}

// ---------------- launch ----------------
typedef CUresult (*PFN_encodeTiled)(CUtensorMap*, CUtensorMapDataType, cuuint32_t, void*,
                                    const cuuint64_t*, const cuuint64_t*, const cuuint32_t*,
                                    const cuuint32_t*, CUtensorMapInterleave, CUtensorMapSwizzle,
                                    CUtensorMapL2promotion, CUtensorMapFloatOOBfill);

extern "C" void kernel_launch(void* const* d_in, const int* in_sizes, int n_in,
                              void* d_out, int out_size) {
    (void)in_sizes; (void)n_in; (void)out_size;
    const float* q = (const float*)d_in[0];
    const float* k = (const float*)d_in[1];
    float* out = (float*)d_out;

    void* fn = nullptr;
    cudaDriverEntryPointQueryResult st;
    cudaGetDriverEntryPoint("cuTensorMapEncodeTiled", &fn, cudaEnableDefault, &st);
    PFN_encodeTiled encode = (PFN_encodeTiled)fn;

    void *pQ = nullptr, *pK = nullptr;
    cudaGetSymbolAddress(&pQ, g_Q8);
    cudaGetSymbolAddress(&pK, g_K8);

    cuuint64_t dims[2] = {DIM, BSZ};
    cuuint64_t strides[1] = {DIM};
    cuuint32_t boxA[2] = {128, TM};
    cuuint32_t boxB[2] = {128, TN};
    cuuint32_t es[2] = {1, 1};

    CUtensorMap tA, tB;
    encode(&tA, CU_TENSOR_MAP_DATA_TYPE_UINT8, 2, pQ, dims, strides, boxA, es,
           CU_TENSOR_MAP_INTERLEAVE_NONE, CU_TENSOR_MAP_SWIZZLE_128B,
           CU_TENSOR_MAP_L2_PROMOTION_L2_128B, CU_TENSOR_MAP_FLOAT_OOB_FILL_NONE);
    encode(&tB, CU_TENSOR_MAP_DATA_TYPE_UINT8, 2, pK, dims, strides, boxB, es,
           CU_TENSOR_MAP_INTERLEAVE_NONE, CU_TENSOR_MAP_SWIZZLE_128B,
           CU_TENSOR_MAP_L2_PROMOTION_L2_128B, CU_TENSOR_MAP_FLOAT_OOB_FILL_NONE);

    cudaFuncSetAttribute(k_gemm, cudaFuncAttributeMaxDynamicSharedMemorySize, SMEM_BYTES);

    k_norm<<<BSZ, 128>>>(q, k, out);
    k_gemm<<<dim3(BSZ / TN, BSZ / TM), 256, SMEM_BYTES>>>(tA, tB);
    k_loss<<<BSZ / 128, 128>>>(out);
}

// round 7
// speedup vs baseline: 1.7800x; 1.1123x over previous
#include <cuda_runtime.h>
#include <cuda.h>
#include <cuda_bf16.h>
#include <cstdint>

#define BSZ 8192
#define DIM 512
#define TM 128
#define TN 256
#define NTI (BSZ / TM)      // 64
#define NTJ (BSZ / TN)      // 32
#define NTILES (NTI * NTJ)  // 2048
#define NSTAGE 4
#define STA 16384           // A stage: 128 rows x 128 B
#define STB 32768           // B stage: 256 rows x 128 B
#define STAGE_BYTES (STA + STB)
#define SMEM_BYTES (1024 + NSTAGE * STAGE_BYTES)
#define TEMP_INV 2.0f
#define LOSS_EPS 1e-5f

// ---------------- scratch (device globals; allocation is forbidden) ----------------
__device__ __align__(1024) signed char g_Q8[BSZ * DIM];
__device__ __align__(1024) signed char g_K8[BSZ * DIM];
__device__ float g_Sq[BSZ];
__device__ float g_Sk[BSZ];
__device__ float g_diag[BSZ];
__device__ float g_Row[BSZ];
__device__ float g_Col[BSZ];

#define SWZ(x) ((x) ^ (((x) >> 3) & 0x70))

static __device__ __forceinline__ uint32_t smem_u32(const void* p) {
    uint32_t a;
    asm("{ .reg .u64 t; cvta.to.shared.u64 t, %1; cvt.u32.u64 %0, t; }"
        : "=r"(a) : "l"(p));
    return a;
}

static __device__ __forceinline__ void ldm_x4(uint32_t* r, uint32_t addr) {
    asm volatile("ldmatrix.sync.aligned.m8n8.x4.shared.b16 {%0,%1,%2,%3}, [%4];"
                 : "=r"(r[0]), "=r"(r[1]), "=r"(r[2]), "=r"(r[3]) : "r"(addr));
}

static __device__ __forceinline__ void mma_s8(int* c, const uint32_t* a, const uint32_t* b) {
    asm volatile(
        "mma.sync.aligned.m16n8k32.row.col.s32.s8.s8.s32 "
        "{%0,%1,%2,%3}, {%4,%5,%6,%7}, {%8,%9}, {%0,%1,%2,%3};"
        : "+r"(c[0]), "+r"(c[1]), "+r"(c[2]), "+r"(c[3])
        : "r"(a[0]), "r"(a[1]), "r"(a[2]), "r"(a[3]), "r"(b[0]), "r"(b[1]));
}

static __device__ __forceinline__ void mbar_init(uint32_t mbar, uint32_t cnt) {
    asm volatile("mbarrier.init.shared.b64 [%0], %1;" :: "r"(mbar), "r"(cnt) : "memory");
}
static __device__ __forceinline__ void mbar_expect_tx(uint32_t mbar, uint32_t bytes) {
    asm volatile("mbarrier.arrive.expect_tx.shared.b64 _, [%0], %1;"
                 :: "r"(mbar), "r"(bytes) : "memory");
}
static __device__ __forceinline__ void mbar_arrive(uint32_t mbar) {
    asm volatile("mbarrier.arrive.shared.b64 _, [%0];" :: "r"(mbar) : "memory");
}
static __device__ __forceinline__ void mbar_wait(uint32_t mbar, uint32_t parity) {
    uint32_t done;
    asm volatile(
        "{\n\t.reg .pred p;\n\t"
        "mbarrier.try_wait.parity.acquire.cta.shared::cta.b64 p, [%1], %2;\n\t"
        "selp.b32 %0, 1, 0, p;\n\t}"
        : "=r"(done) : "r"(mbar), "r"(parity) : "memory");
    if (!done) {
        asm volatile(
            "{\n\t.reg .pred P1;\n\t"
            "W_LOOP_%=:\n\t"
            "mbarrier.try_wait.parity.acquire.cta.shared::cta.b64 P1, [%0], %1, 0x989680;\n\t"
            "@P1 bra.uni W_DONE_%=;\n\t"
            "bra.uni W_LOOP_%=;\n\t"
            "W_DONE_%=:\n\t}"
            :: "r"(mbar), "r"(parity) : "memory");
    }
}
static __device__ __forceinline__ void tma_2d(uint32_t saddr, const CUtensorMap* tmap,
                                              int x, int y, uint32_t mbar) {
    asm volatile(
        "cp.async.bulk.tensor.2d.shared::cta.global.tile.mbarrier::complete_tx::bytes "
        "[%0], [%1, {%2, %3}], [%4];"
        :: "r"(saddr), "l"(tmap), "r"(x), "r"(y), "r"(mbar) : "memory");
}

// ---------------- kernel 0: warp-per-row normalize + int8 quantize ----------------
static __device__ __forceinline__ float wsum(float v) {
    #pragma unroll
    for (int o = 16; o; o >>= 1) v += __shfl_xor_sync(0xffffffffu, v, o);
    return v;
}
static __device__ __forceinline__ float wmax(float v) {
    #pragma unroll
    for (int o = 16; o; o >>= 1) v = fmaxf(v, __shfl_xor_sync(0xffffffffu, v, o));
    return v;
}

__global__ void __launch_bounds__(256) k_norm(const float* __restrict__ q,
                                              const float* __restrict__ k,
                                              float* __restrict__ out) {
    const int lane = threadIdx.x & 31;
    const int row = blockIdx.x * 8 + (threadIdx.x >> 5);
    const float4* qr = (const float4*)(q + (size_t)row * DIM);
    const float4* kr = (const float4*)(k + (size_t)row * DIM);

    float a[16], b[16];
    #pragma unroll
    for (int i = 0; i < 4; i++) {
        float4 v = qr[lane + 32 * i];
        a[4 * i] = v.x; a[4 * i + 1] = v.y; a[4 * i + 2] = v.z; a[4 * i + 3] = v.w;
        float4 w = kr[lane + 32 * i];
        b[4 * i] = w.x; b[4 * i + 1] = w.y; b[4 * i + 2] = w.z; b[4 * i + 3] = w.w;
    }

    float sq = 0.f, sk = 0.f;
    #pragma unroll
    for (int i = 0; i < 16; i++) { sq += a[i] * a[i]; sk += b[i] * b[i]; }
    sq = wsum(sq); sk = wsum(sk);
    const float iq = 1.0f / fmaxf(sqrtf(sq), 1e-12f);
    const float ik = 1.0f / fmaxf(sqrtf(sk), 1e-12f);

    float dot = 0.f, mq = 0.f, mk = 0.f;
    #pragma unroll
    for (int i = 0; i < 16; i++) {
        a[i] *= iq; b[i] *= ik;
        dot += a[i] * b[i];
        mq = fmaxf(mq, fabsf(a[i]));
        mk = fmaxf(mk, fabsf(b[i]));
    }
    dot = wsum(dot);
    mq = fmaxf(wmax(mq), 1e-20f);
    mk = fmaxf(wmax(mk), 1e-20f);

    const float qa = 127.0f / mq, qb = 127.0f / mk;
    #pragma unroll
    for (int i = 0; i < 4; i++) {
        char4 ca, cb;
        ca.x = (char)__float2int_rn(a[4 * i] * qa);
        ca.y = (char)__float2int_rn(a[4 * i + 1] * qa);
        ca.z = (char)__float2int_rn(a[4 * i + 2] * qa);
        ca.w = (char)__float2int_rn(a[4 * i + 3] * qa);
        cb.x = (char)__float2int_rn(b[4 * i] * qb);
        cb.y = (char)__float2int_rn(b[4 * i + 1] * qb);
        cb.z = (char)__float2int_rn(b[4 * i + 2] * qb);
        cb.w = (char)__float2int_rn(b[4 * i + 3] * qb);
        ((char4*)g_Q8)[(size_t)row * 128 + lane + 32 * i] = ca;
        ((char4*)g_K8)[(size_t)row * 128 + lane + 32 * i] = cb;
    }

    if (lane == 0) {
        g_Sq[row] = mq * (1.0f / 127.0f);
        g_Sk[row] = mk * (1.0f / 127.0f);
        g_diag[row] = dot;
        g_Row[row] = 0.f;
        g_Col[row] = 0.f;
        if (row == 0) out[0] = 0.f;
    }
}

// ---------------- kernel 1: persistent int8 IMMA, cross-tile 4-stage TMA ring ----------------
__global__ void __launch_bounds__(256, 1) k_gemm(const __grid_constant__ CUtensorMap tmapA,
                                                const __grid_constant__ CUtensorMap tmapB) {
    extern __shared__ __align__(1024) char smem[];
    const uint32_t sbase = smem_u32(smem);
    const int tid = threadIdx.x, wid = tid >> 5, lane = tid & 31;
    const int warp_m = wid & 1;
    const int warp_n = wid >> 1;
    const int bid = blockIdx.x, G = gridDim.x;
    const int ntiles = (NTILES - 1 - bid) / G + 1;
    const int gtot = ntiles * 4;

    if (tid == 0) {
        #pragma unroll
        for (int s = 0; s < NSTAGE; s++) {
            mbar_init(sbase + s * 16, 1);       // full (tx-based)
            mbar_init(sbase + s * 16 + 8, 8);   // empty (one arrive per warp)
        }
    }
    __syncthreads();

    auto produce = [&](int gp) {
        const int t = bid + (gp >> 2) * G;
        const int s = gp & 3;
        const uint32_t stA = sbase + 1024 + s * STAGE_BYTES;
        const uint32_t fullb = sbase + s * 16;
        mbar_expect_tx(fullb, STAGE_BYTES);
        tma_2d(stA, &tmapA, (gp & 3) * 128, (t >> 5) * TM, fullb);
        tma_2d(stA + STA, &tmapB, (gp & 3) * 128, (t & 31) * TN, fullb);
    };

    if (tid == 0) {
        #pragma unroll
        for (int gp = 0; gp < NSTAGE; gp++) produce(gp);   // gtot >= 4 always
    }

    // ldmatrix geometry (verified)
    const int lg = lane >> 3;
    const int a_row = warp_m * 64 + (lane & 7) + ((lg & 1) << 3);
    const int a_kb = (lg >> 1) << 4;
    const int b_row = warp_n * 64 + (lane & 7) + ((lg >> 1) << 3);
    const int b_kb = (lg & 1) << 4;
    const int g8 = lane >> 2, qq = lane & 3;

    int g = 0;
    #pragma unroll 1
    for (int il = 0; il < ntiles; il++) {
        const int t = bid + il * G;
        const int ti = t >> 5, tj = t & 31;

        int acc[4][8][4];
        #pragma unroll
        for (int mi = 0; mi < 4; mi++)
            #pragma unroll
            for (int ni = 0; ni < 8; ni++)
                #pragma unroll
                for (int e = 0; e < 4; e++) acc[mi][ni][e] = 0;

        #pragma unroll 1
        for (int c = 0; c < 4; c++) {
            const int s = g & 3;
            const uint32_t fullb = sbase + s * 16;
            const uint32_t emptyb = fullb + 8;
            mbar_wait(fullb, (g >> 2) & 1);
            const uint32_t sA = sbase + 1024 + s * STAGE_BYTES;
            const uint32_t sB = sA + STA;

            #pragma unroll
            for (int ks = 0; ks < 4; ks++) {
                const int kb = ks * 32;
                uint32_t a[4][4];
                #pragma unroll
                for (int mi = 0; mi < 4; mi++)
                    ldm_x4(a[mi], sA + SWZ((a_row + mi * 16) * 128 + kb + a_kb));
                #pragma unroll
                for (int np = 0; np < 4; np++) {
                    uint32_t b[4];
                    ldm_x4(b, sB + SWZ((b_row + np * 16) * 128 + kb + b_kb));
                    #pragma unroll
                    for (int mi = 0; mi < 4; mi++) {
                        mma_s8(acc[mi][np * 2 + 0], a[mi], b + 0);
                        mma_s8(acc[mi][np * 2 + 1], a[mi], b + 2);
                    }
                }
            }

            __syncwarp();
            if (lane == 0) mbar_arrive(emptyb);
            if (tid == 0 && g + NSTAGE < gtot) {
                mbar_wait(emptyb, (g >> 2) & 1);   // all 8 warps done with stage s
                produce(g + NSTAGE);
            }
            g++;
        }

        // ---- epilogue: dequant + exp + row/col sums (next tile's TMA in flight) ----
        float rA[4][2], rB[8][2];
        #pragma unroll
        for (int mi = 0; mi < 4; mi++) {
            const int r0 = ti * TM + warp_m * 64 + mi * 16 + g8;
            rA[mi][0] = g_Sq[r0] * TEMP_INV;
            rA[mi][1] = g_Sq[r0 + 8] * TEMP_INV;
        }
        #pragma unroll
        for (int ni = 0; ni < 8; ni++) {
            const int c0 = tj * TN + warp_n * 64 + ni * 8 + qq * 2;
            rB[ni][0] = g_Sk[c0];
            rB[ni][1] = g_Sk[c0 + 1];
        }

        float rs0[4] = {0.f, 0.f, 0.f, 0.f}, rs8[4] = {0.f, 0.f, 0.f, 0.f};
        float cs[8][2];
        #pragma unroll
        for (int ni = 0; ni < 8; ni++) cs[ni][0] = cs[ni][1] = 0.f;

        #pragma unroll
        for (int mi = 0; mi < 4; mi++)
            #pragma unroll
            for (int ni = 0; ni < 8; ni++) {
                float e0 = __expf((float)acc[mi][ni][0] * (rA[mi][0] * rB[ni][0]));
                float e1 = __expf((float)acc[mi][ni][1] * (rA[mi][0] * rB[ni][1]));
                float e2 = __expf((float)acc[mi][ni][2] * (rA[mi][1] * rB[ni][0]));
                float e3 = __expf((float)acc[mi][ni][3] * (rA[mi][1] * rB[ni][1]));
                rs0[mi] += e0 + e1;
                rs8[mi] += e2 + e3;
                cs[ni][0] += e0 + e2;
                cs[ni][1] += e1 + e3;
            }

        #pragma unroll
        for (int mi = 0; mi < 4; mi++) {
            rs0[mi] += __shfl_xor_sync(0xffffffffu, rs0[mi], 1);
            rs0[mi] += __shfl_xor_sync(0xffffffffu, rs0[mi], 2);
            rs8[mi] += __shfl_xor_sync(0xffffffffu, rs8[mi], 1);
            rs8[mi] += __shfl_xor_sync(0xffffffffu, rs8[mi], 2);
        }
        if ((lane & 3) == 0) {
            const int rbase = ti * TM + warp_m * 64 + g8;
            #pragma unroll
            for (int mi = 0; mi < 4; mi++) {
                atomicAdd(&g_Row[rbase + mi * 16], rs0[mi]);
                atomicAdd(&g_Row[rbase + mi * 16 + 8], rs8[mi]);
            }
        }

        #pragma unroll
        for (int ni = 0; ni < 8; ni++)
            #pragma unroll
            for (int j = 0; j < 2; j++) {
                cs[ni][j] += __shfl_xor_sync(0xffffffffu, cs[ni][j], 4);
                cs[ni][j] += __shfl_xor_sync(0xffffffffu, cs[ni][j], 8);
                cs[ni][j] += __shfl_xor_sync(0xffffffffu, cs[ni][j], 16);
            }
        if (lane < 4) {
            const int cbase = tj * TN + warp_n * 64 + lane * 2;
            #pragma unroll
            for (int ni = 0; ni < 8; ni++) {
                atomicAdd(&g_Col[cbase + ni * 8], cs[ni][0]);
                atomicAdd(&g_Col[cbase + ni * 8 + 1], cs[ni][1]);
            }
        }
    }
}

// ---------------- kernel 2: final loss ----------------
__global__ void __launch_bounds__(128) k_loss(float* __restrict__ out) {
    __shared__ float sb[4];
    const int i = blockIdx.x * 128 + threadIdx.x;
    const float rs = g_Row[i], cs = g_Col[i], d = g_diag[i];
    const float ep = __expf(d * TEMP_INV);
    float term = -logf(ep / rs + LOSS_EPS) - logf(ep / cs + LOSS_EPS);
    #pragma unroll
    for (int o = 16; o; o >>= 1) term += __shfl_xor_sync(0xffffffffu, term, o);
    __syncthreads();
    if ((threadIdx.x & 31) == 0) sb[threadIdx.x >> 5] = term;
    __syncthreads();
    if (threadIdx.x == 0)
        atomicAdd(out, ((sb[0] + sb[1]) + (sb[2] + sb[3])) * (1.0f / (float)BSZ));
}

// ---------------- launch ----------------
typedef CUresult (*PFN_encodeTiled)(CUtensorMap*, CUtensorMapDataType, cuuint32_t, void*,
                                    const cuuint64_t*, const cuuint64_t*, const cuuint32_t*,
                                    const cuuint32_t*, CUtensorMapInterleave, CUtensorMapSwizzle,
                                    CUtensorMapL2promotion, CUtensorMapFloatOOBfill);

extern "C" void kernel_launch(void* const* d_in, const int* in_sizes, int n_in,
                              void* d_out, int out_size) {
    (void)in_sizes; (void)n_in; (void)out_size;
    const float* q = (const float*)d_in[0];
    const float* k = (const float*)d_in[1];
    float* out = (float*)d_out;

    void* fn = nullptr;
    cudaDriverEntryPointQueryResult st;
    cudaGetDriverEntryPoint("cuTensorMapEncodeTiled", &fn, cudaEnableDefault, &st);
    PFN_encodeTiled encode = (PFN_encodeTiled)fn;

    void *pQ = nullptr, *pK = nullptr;
    cudaGetSymbolAddress(&pQ, g_Q8);
    cudaGetSymbolAddress(&pK, g_K8);

    cuuint64_t dims[2] = {DIM, BSZ};
    cuuint64_t strides[1] = {DIM};
    cuuint32_t boxA[2] = {128, TM};
    cuuint32_t boxB[2] = {128, TN};
    cuuint32_t es[2] = {1, 1};

    CUtensorMap tA, tB;
    encode(&tA, CU_TENSOR_MAP_DATA_TYPE_UINT8, 2, pQ, dims, strides, boxA, es,
           CU_TENSOR_MAP_INTERLEAVE_NONE, CU_TENSOR_MAP_SWIZZLE_128B,
           CU_TENSOR_MAP_L2_PROMOTION_L2_128B, CU_TENSOR_MAP_FLOAT_OOB_FILL_NONE);
    encode(&tB, CU_TENSOR_MAP_DATA_TYPE_UINT8, 2, pK, dims, strides, boxB, es,
           CU_TENSOR_MAP_INTERLEAVE_NONE, CU_TENSOR_MAP_SWIZZLE_128B,
           CU_TENSOR_MAP_L2_PROMOTION_L2_128B, CU_TENSOR_MAP_FLOAT_OOB_FILL_NONE);

    int nsm = 148;
    cudaDeviceGetAttribute(&nsm, cudaDevAttrMultiProcessorCount, 0);

    cudaFuncSetAttribute(k_gemm, cudaFuncAttributeMaxDynamicSharedMemorySize, SMEM_BYTES);

    k_norm<<<BSZ / 8, 256>>>(q, k, out);
    k_gemm<<<nsm, 256, SMEM_BYTES>>>(tA, tB);
    k_loss<<<BSZ / 128, 128>>>(out);
}